// round 5
// baseline (speedup 1.0000x reference)
#include <cuda_runtime.h>
#include <math.h>

#define D 128
#define ND3 384
#define T_STEPS 25
#define B_ROWS 16384
#define RTOT (B_ROWS * T_STEPS)   // 409600 rows for the time-parallel GEMMs

// Scratch (static __device__ globals -- allocation-free per harness rules)
__device__ float g_xw[(size_t)RTOT * ND3];   // xW projections for current layer [B*T, 384]
__device__ float g_h1[(size_t)RTOT * D];     // layer-1 hidden sequence [B*T, 128]
__device__ float g_h2[(size_t)B_ROWS * D];   // layer-2 final hidden [B, 128]

__device__ __forceinline__ float sigmoidf_fast(float x) {
    return 1.0f / (1.0f + __expf(-x));
}

// ---------------------------------------------------------------------------
// Generic row-parallel GEMM: G[r, c] = sum_k X[r, k] * W[k, c]
// X: [nrows, 128], W: [128, NC], G: [nrows, NC].
// CTA: 256 threads, 32 rows per row-block. Each thread: 4 rows x (NC/32) cols.
// W cached in SMEM (loaded once per CTA; CTA loops over row-blocks).
// ---------------------------------------------------------------------------
template <int NC>
__global__ void __launch_bounds__(256, 1)
gemm_k(const float* __restrict__ X, const float* __restrict__ W,
       float* __restrict__ G, int nrowblocks)
{
    constexpr int J = NC / 32;
    extern __shared__ float sm[];
    float* Ws = sm;            // [128 * NC]
    float* xs = sm + D * NC;   // [32 * 128]

    const int tid = threadIdx.x;
    // Vectorized weight stage: D*NC floats = D*NC/4 float4s
    {
        const float4* Wv = (const float4*)W;
        float4* Wsv = (float4*)Ws;
        for (int i = tid; i < D * NC / 4; i += 256) Wsv[i] = Wv[i];
    }

    const int tx = tid & 31;
    const int ty = tid >> 5;
    const int r0 = ty * 4;

    for (int rb = blockIdx.x; rb < nrowblocks; rb += gridDim.x) {
        const size_t rowbase = (size_t)rb * 32;
        __syncthreads();   // prior iteration's xs reads done (also orders Ws stage)
        {
            const float4* Xv = (const float4*)(X + rowbase * D);
            float4* xsv = (float4*)xs;
            #pragma unroll
            for (int i = 0; i < (32 * D / 4) / 256; i++) xsv[tid + 256 * i] = Xv[tid + 256 * i];
        }
        __syncthreads();   // xs (and Ws) visible

        float acc[4][J];
        #pragma unroll
        for (int i = 0; i < 4; i++)
            #pragma unroll
            for (int j = 0; j < J; j++) acc[i][j] = 0.0f;

        #pragma unroll 4
        for (int k = 0; k < D; k++) {
            const float a0 = xs[(r0 + 0) * D + k];
            const float a1 = xs[(r0 + 1) * D + k];
            const float a2 = xs[(r0 + 2) * D + k];
            const float a3 = xs[(r0 + 3) * D + k];
            #pragma unroll
            for (int j = 0; j < J; j++) {
                const float b = Ws[k * NC + tx + 32 * j];
                acc[0][j] = fmaf(a0, b, acc[0][j]);
                acc[1][j] = fmaf(a1, b, acc[1][j]);
                acc[2][j] = fmaf(a2, b, acc[2][j]);
                acc[3][j] = fmaf(a3, b, acc[3][j]);
            }
        }

        #pragma unroll
        for (int i = 0; i < 4; i++) {
            const size_t go = (rowbase + r0 + i) * NC;
            #pragma unroll
            for (int j = 0; j < J; j++) G[go + tx + 32 * j] = acc[i][j];
        }
    }
}

// ---------------------------------------------------------------------------
// GRU scan over T steps. Each CTA owns 32 batch rows; recurrence is private
// to the CTA (no grid sync). U (128x384) lives in SMEM; h (32x128) in SMEM.
// G: precomputed x@W gate inputs, layout [B, T, 384].
// STORE_SEQ: write h at every step to Hout [B, T, 128]; else only final
// state to Hout [B, 128].
// ---------------------------------------------------------------------------
template <bool STORE_SEQ>
__global__ void __launch_bounds__(256, 1)
gru_scan(const float* __restrict__ G, const float* __restrict__ U,
         float* __restrict__ Hout)
{
    extern __shared__ float sm[];
    float* Us = sm;             // [128 * 384]
    float* hs = sm + D * ND3;   // [32 * 128]

    const int tid = threadIdx.x;
    {
        const float4* Uv = (const float4*)U;
        float4* Usv = (float4*)Us;
        for (int i = tid; i < D * ND3 / 4; i += 256) Usv[i] = Uv[i];
        float4* hsv = (float4*)hs;
        const float4 z4 = make_float4(0.f, 0.f, 0.f, 0.f);
        #pragma unroll
        for (int i = 0; i < (32 * D / 4) / 256; i++) hsv[tid + 256 * i] = z4;
    }

    const int tx = tid & 31;
    const int ty = tid >> 5;
    const int r0 = ty * 4;
    const size_t rowbase = (size_t)blockIdx.x * 32;

    for (int t = 0; t < T_STEPS; t++) {
        __syncthreads();  // Us/hs ready; previous step's hs writes visible

        // hU = h @ U : acc[i][j] = sum_k hs[r0+i][k] * U[k][tx+32j]
        float acc[4][12];
        #pragma unroll
        for (int i = 0; i < 4; i++)
            #pragma unroll
            for (int j = 0; j < 12; j++) acc[i][j] = 0.0f;

        #pragma unroll 4
        for (int k = 0; k < D; k++) {
            const float a0 = hs[(r0 + 0) * D + k];
            const float a1 = hs[(r0 + 1) * D + k];
            const float a2 = hs[(r0 + 2) * D + k];
            const float a3 = hs[(r0 + 3) * D + k];
            #pragma unroll
            for (int j = 0; j < 12; j++) {
                const float b = Us[k * ND3 + tx + 32 * j];
                acc[0][j] = fmaf(a0, b, acc[0][j]);
                acc[1][j] = fmaf(a1, b, acc[1][j]);
                acc[2][j] = fmaf(a2, b, acc[2][j]);
                acc[3][j] = fmaf(a3, b, acc[3][j]);
            }
        }

        __syncthreads();  // all hs reads complete before anyone updates hs

        // Gates + state update. Thread owns h cells (row in its 4 rows,
        // col = tx + 32*jj), so the write below races with nobody.
        #pragma unroll
        for (int i = 0; i < 4; i++) {
            const int row = r0 + i;
            const size_t go = ((rowbase + row) * T_STEPS + t) * ND3;
            #pragma unroll
            for (int jj = 0; jj < 4; jj++) {
                const int c = tx + 32 * jj;
                const float xz = G[go + c];
                const float xr = G[go + 128 + c];
                const float xh = G[go + 256 + c];
                const float z = sigmoidf_fast(xz + acc[i][jj]);
                const float r = sigmoidf_fast(xr + acc[i][4 + jj]);
                const float hh = xh + r * acc[i][8 + jj];     // reset_after, linear act
                const float hold = hs[row * D + c];
                const float hnew = z * hold + (1.0f - z) * hh;
                hs[row * D + c] = hnew;
                if (STORE_SEQ) {
                    Hout[((rowbase + row) * T_STEPS + t) * D + c] = hnew;
                } else if (t == T_STEPS - 1) {
                    Hout[(rowbase + row) * D + c] = hnew;
                }
            }
        }
    }
}

// ---------------------------------------------------------------------------
// kernel_launch: 5 graph-capturable launches, no allocs, no syncs.
// Inputs (metadata order): x, W1, U1, W2, U2, Wout. Output: [16384,128] f32.
// ---------------------------------------------------------------------------
extern "C" void kernel_launch(void* const* d_in, const int* in_sizes, int n_in,
                              void* d_out, int out_size)
{
    const float* x    = (const float*)d_in[0];
    const float* W1   = (const float*)d_in[1];
    const float* U1   = (const float*)d_in[2];
    const float* W2   = (const float*)d_in[3];
    const float* U2   = (const float*)d_in[4];
    const float* Wout = (const float*)d_in[5];
    float* out = (float*)d_out;

    void *p_xw = nullptr, *p_h1 = nullptr, *p_h2 = nullptr;
    cudaGetSymbolAddress(&p_xw, g_xw);
    cudaGetSymbolAddress(&p_h1, g_h1);
    cudaGetSymbolAddress(&p_h2, g_h2);
    float* gxw = (float*)p_xw;
    float* gh1 = (float*)p_h1;
    float* gh2 = (float*)p_h2;

    const size_t smem_big = (size_t)(D * ND3 + 32 * D) * sizeof(float);   // 208 KB
    const size_t smem_out = (size_t)(D * 128 + 32 * D) * sizeof(float);   // 80 KB

    cudaFuncSetAttribute(gemm_k<384>, cudaFuncAttributeMaxDynamicSharedMemorySize, (int)smem_big);
    cudaFuncSetAttribute(gemm_k<128>, cudaFuncAttributeMaxDynamicSharedMemorySize, (int)smem_out);
    cudaFuncSetAttribute(gru_scan<true>,  cudaFuncAttributeMaxDynamicSharedMemorySize, (int)smem_big);
    cudaFuncSetAttribute(gru_scan<false>, cudaFuncAttributeMaxDynamicSharedMemorySize, (int)smem_big);

    const int nrb_big = RTOT / 32;     // 12800 row-blocks of 32
    const int nrb_out = B_ROWS / 32;   // 512

    // Layer 1: x @ W1 -> g_xw
    gemm_k<384><<<512, 256, smem_big>>>(x, W1, gxw, nrb_big);
    // Layer 1 scan (store full sequence)
    gru_scan<true><<<B_ROWS / 32, 256, smem_big>>>(gxw, U1, gh1);
    // Layer 2: h1seq @ W2 -> g_xw (reuse)
    gemm_k<384><<<512, 256, smem_big>>>(gh1, W2, gxw, nrb_big);
    // Layer 2 scan (final state only)
    gru_scan<false><<<B_ROWS / 32, 256, smem_big>>>(gxw, U2, gh2);
    // Output projection: h2 @ Wout -> out
    gemm_k<128><<<512, 256, smem_out>>>(gh2, Wout, out, nrb_out);
}

// round 6
// speedup vs baseline: 1.2645x; 1.2645x over previous
#include <cuda_runtime.h>
#include <math.h>

#define D 128
#define ND3 384
#define T_STEPS 25
#define B_ROWS 16384
#define RTOT (B_ROWS * T_STEPS)   // 409600 rows for the time-parallel GEMMs

// Scratch (static __device__ globals -- allocation-free per harness rules)
__device__ float g_xw[(size_t)RTOT * ND3];   // xW projections for current layer [B*T, 384]
__device__ float g_h1[(size_t)RTOT * D];     // layer-1 hidden sequence [B*T, 128]
__device__ float g_h2[(size_t)B_ROWS * D];   // layer-2 final hidden [B, 128]

typedef unsigned long long ull;

__device__ __forceinline__ float sigmoidf_fast(float x) {
    return 1.0f / (1.0f + __expf(-x));
}

// Packed fp32x2 helpers (Blackwell FFMA2 -- only reachable via PTX fma.rn.f32x2)
__device__ __forceinline__ ull pack2(float lo, float hi) {
    ull r;
    asm("mov.b64 %0, {%1, %2};" : "=l"(r) : "f"(lo), "f"(hi));
    return r;
}
__device__ __forceinline__ void unpack2(ull v, float& lo, float& hi) {
    asm("mov.b64 {%0, %1}, %2;" : "=f"(lo), "=f"(hi) : "l"(v));
}
__device__ __forceinline__ ull ffma2(ull a, ull b, ull c) {
    ull d;
    asm("fma.rn.f32x2 %0, %1, %2, %3;" : "=l"(d) : "l"(a), "l"(b), "l"(c));
    return d;
}

// ---------------------------------------------------------------------------
// Row-parallel GEMM via FFMA2: G[r, c] = sum_k X[r, k] * W[k, c]
// X: [nrows,128], W: [128,NC], G: [nrows,NC]. CTA: 256 thr, 32-row blocks.
// Each thread: 4 rows x (NC/64) column-PAIRS. W in smem (plain); X row block
// staged DUPLICATED as (a,a) 8-byte pairs so the broadcast operand is a
// single LDS.64.
// ---------------------------------------------------------------------------
template <int NC>
__global__ void __launch_bounds__(256, 1)
gemm_k(const float* __restrict__ X, const float* __restrict__ W,
       float* __restrict__ G, int nrowblocks)
{
    constexpr int PJ = NC / 64;       // column pairs per thread
    constexpr int NCH = NC / 2;       // pair-stride of one W row
    extern __shared__ float sm[];
    float* Ws = sm;                                   // [128*NC] floats
    ull*   xs2 = (ull*)(sm + D * NC);                 // [32*128] dup pairs
    const ull* Wsv = (const ull*)Ws;

    const int tid = threadIdx.x;
    {   // stage W (vectorized)
        const float4* Wv = (const float4*)W;
        float4* Wst = (float4*)Ws;
        for (int i = tid; i < D * NC / 4; i += 256) Wst[i] = Wv[i];
    }

    const int tx = tid & 31;
    const int ty = tid >> 5;
    const int r0 = ty * 4;

    for (int rb = blockIdx.x; rb < nrowblocks; rb += gridDim.x) {
        const size_t rowbase = (size_t)rb * 32;
        __syncthreads();   // prior block's xs2 reads done
        {   // stage X block duplicated: xs2[i] = (x_i, x_i)
            const float4* Xv = (const float4*)(X + rowbase * D);
            #pragma unroll
            for (int i = tid; i < 32 * D / 4; i += 256) {
                float4 v = Xv[i];
                xs2[4 * i + 0] = pack2(v.x, v.x);
                xs2[4 * i + 1] = pack2(v.y, v.y);
                xs2[4 * i + 2] = pack2(v.z, v.z);
                xs2[4 * i + 3] = pack2(v.w, v.w);
            }
        }
        __syncthreads();

        ull acc[4][PJ];
        #pragma unroll
        for (int i = 0; i < 4; i++)
            #pragma unroll
            for (int j = 0; j < PJ; j++) acc[i][j] = 0ULL;

        #pragma unroll 4
        for (int k = 0; k < D; k++) {
            const ull a0 = xs2[(r0 + 0) * D + k];
            const ull a1 = xs2[(r0 + 1) * D + k];
            const ull a2 = xs2[(r0 + 2) * D + k];
            const ull a3 = xs2[(r0 + 3) * D + k];
            #pragma unroll
            for (int j = 0; j < PJ; j++) {
                const ull b = Wsv[k * NCH + 32 * j + tx];   // cols (64j+2tx, +1)
                acc[0][j] = ffma2(a0, b, acc[0][j]);
                acc[1][j] = ffma2(a1, b, acc[1][j]);
                acc[2][j] = ffma2(a2, b, acc[2][j]);
                acc[3][j] = ffma2(a3, b, acc[3][j]);
            }
        }

        #pragma unroll
        for (int i = 0; i < 4; i++) {
            float2* G2 = (float2*)(G + (rowbase + r0 + i) * NC);
            #pragma unroll
            for (int j = 0; j < PJ; j++) {
                float lo, hi; unpack2(acc[i][j], lo, hi);
                G2[32 * j + tx] = make_float2(lo, hi);
            }
        }
    }
}

// ---------------------------------------------------------------------------
// GRU scan via FFMA2. Persistent CTAs grid-stride over 16-row blocks
// (B/16 = 1024 blocks -> ~1% wave imbalance at 148 CTAs). U resident in smem
// (staged once per CTA). h state lives in REGISTERS (each thread owns its
// 8 cells across all steps) and is mirrored duplicated into hs2 for the
// next step's k-dimension reads.
// ---------------------------------------------------------------------------
template <bool STORE_SEQ>
__global__ void __launch_bounds__(256, 1)
gru_scan(const float* __restrict__ G, const float* __restrict__ U,
         float* __restrict__ Hout, int nblocks)
{
    constexpr int NDH = ND3 / 2;   // 192 pair-stride
    extern __shared__ float sm[];
    float* Us = sm;                                   // [128*384]
    ull*   hs2 = (ull*)(sm + D * ND3);                // [16*128] dup pairs
    const ull* Usv = (const ull*)Us;

    const int tid = threadIdx.x;
    {   // stage U once per CTA
        const float4* Uv = (const float4*)U;
        float4* Ust = (float4*)Us;
        for (int i = tid; i < D * ND3 / 4; i += 256) Ust[i] = Uv[i];
    }

    const int tx = tid & 31;
    const int ty = tid >> 5;
    const int r0 = ty * 2;   // 2 rows per thread, 16 rows per block

    for (int blk = blockIdx.x; blk < nblocks; blk += gridDim.x) {
        const size_t rowbase = (size_t)blk * 16;

        __syncthreads();   // prior block fully done before re-zeroing hs2
        for (int i = tid; i < 16 * D; i += 256) hs2[i] = 0ULL;
        float hreg[2][4] = {};   // [row][ 2*jz + s ] : col = 64*jz + 2*tx + s

        for (int t = 0; t < T_STEPS; t++) {
            __syncthreads();   // hs2 (and Us on t=0,blk=first) visible

            ull acc[2][6];
            #pragma unroll
            for (int i = 0; i < 2; i++)
                #pragma unroll
                for (int j = 0; j < 6; j++) acc[i][j] = 0ULL;

            #pragma unroll 4
            for (int k = 0; k < D; k++) {
                const ull a0 = hs2[(r0 + 0) * D + k];
                const ull a1 = hs2[(r0 + 1) * D + k];
                #pragma unroll
                for (int j = 0; j < 6; j++) {
                    const ull b = Usv[k * NDH + 32 * j + tx];
                    acc[0][j] = ffma2(a0, b, acc[0][j]);
                    acc[1][j] = ffma2(a1, b, acc[1][j]);
                }
            }

            __syncthreads();   // all hs2 reads complete before updates

            #pragma unroll
            for (int i = 0; i < 2; i++) {
                const int row = r0 + i;
                const size_t grow = ((rowbase + row) * T_STEPS + t);
                const float2* G2 = (const float2*)(G + grow * ND3);
                #pragma unroll
                for (int jz = 0; jz < 2; jz++) {
                    // column pair c0 = 64*jz + 2*tx, c0+1
                    const float2 xz = G2[      32 * jz + tx];
                    const float2 xr = G2[ 64 + 32 * jz + tx];
                    const float2 xh = G2[128 + 32 * jz + tx];
                    float uz0, uz1, ur0, ur1, uh0, uh1;
                    unpack2(acc[i][jz],     uz0, uz1);
                    unpack2(acc[i][2 + jz], ur0, ur1);
                    unpack2(acc[i][4 + jz], uh0, uh1);
                    const float z0 = sigmoidf_fast(xz.x + uz0);
                    const float z1 = sigmoidf_fast(xz.y + uz1);
                    const float rr0 = sigmoidf_fast(xr.x + ur0);
                    const float rr1 = sigmoidf_fast(xr.y + ur1);
                    const float hh0 = xh.x + rr0 * uh0;   // reset_after, linear act
                    const float hh1 = xh.y + rr1 * uh1;
                    const float h0 = hreg[i][2 * jz + 0];
                    const float h1 = hreg[i][2 * jz + 1];
                    const float n0 = z0 * h0 + (1.0f - z0) * hh0;
                    const float n1 = z1 * h1 + (1.0f - z1) * hh1;
                    hreg[i][2 * jz + 0] = n0;
                    hreg[i][2 * jz + 1] = n1;
                    const int c0 = 64 * jz + 2 * tx;
                    hs2[row * D + c0]     = pack2(n0, n0);
                    hs2[row * D + c0 + 1] = pack2(n1, n1);
                    if (STORE_SEQ) {
                        float2* H2 = (float2*)(Hout + grow * D);
                        H2[32 * jz + tx] = make_float2(n0, n1);
                    } else if (t == T_STEPS - 1) {
                        float2* H2 = (float2*)(Hout + (rowbase + row) * D);
                        H2[32 * jz + tx] = make_float2(n0, n1);
                    }
                }
            }
        }
    }
}

// ---------------------------------------------------------------------------
// kernel_launch: 5 graph-capturable launches, no allocs, no syncs.
// Inputs (metadata order): x, W1, U1, W2, U2, Wout. Output: [16384,128] f32.
// ---------------------------------------------------------------------------
extern "C" void kernel_launch(void* const* d_in, const int* in_sizes, int n_in,
                              void* d_out, int out_size)
{
    const float* x    = (const float*)d_in[0];
    const float* W1   = (const float*)d_in[1];
    const float* U1   = (const float*)d_in[2];
    const float* W2   = (const float*)d_in[3];
    const float* U2   = (const float*)d_in[4];
    const float* Wout = (const float*)d_in[5];
    float* out = (float*)d_out;

    void *p_xw = nullptr, *p_h1 = nullptr, *p_h2 = nullptr;
    cudaGetSymbolAddress(&p_xw, g_xw);
    cudaGetSymbolAddress(&p_h1, g_h1);
    cudaGetSymbolAddress(&p_h2, g_h2);
    float* gxw = (float*)p_xw;
    float* gh1 = (float*)p_h1;
    float* gh2 = (float*)p_h2;

    // smem sizes
    const size_t smem_g384 = (size_t)D * ND3 * 4 + 32 * D * 8;   // 192KB + 32KB = 229376
    const size_t smem_g128 = (size_t)D * 128 * 4 + 32 * D * 8;   // 64KB + 32KB
    const size_t smem_scan = (size_t)D * ND3 * 4 + 16 * D * 8;   // 192KB + 16KB = 212992

    cudaFuncSetAttribute(gemm_k<384>, cudaFuncAttributeMaxDynamicSharedMemorySize, (int)smem_g384);
    cudaFuncSetAttribute(gemm_k<128>, cudaFuncAttributeMaxDynamicSharedMemorySize, (int)smem_g128);
    cudaFuncSetAttribute(gru_scan<true>,  cudaFuncAttributeMaxDynamicSharedMemorySize, (int)smem_scan);
    cudaFuncSetAttribute(gru_scan<false>, cudaFuncAttributeMaxDynamicSharedMemorySize, (int)smem_scan);

    const int nrb_big  = RTOT / 32;    // 12800 row-blocks of 32
    const int nrb_out  = B_ROWS / 32;  // 512
    const int nblk_scan = B_ROWS / 16; // 1024 scan blocks of 16 rows

    // Layer 1: x @ W1 -> g_xw
    gemm_k<384><<<148, 256, smem_g384>>>(x, W1, gxw, nrb_big);
    // Layer 1 scan (store full sequence)
    gru_scan<true><<<148, 256, smem_scan>>>(gxw, U1, gh1, nblk_scan);
    // Layer 2: h1seq @ W2 -> g_xw (reuse)
    gemm_k<384><<<148, 256, smem_g384>>>(gh1, W2, gxw, nrb_big);
    // Layer 2 scan (final state only)
    gru_scan<false><<<148, 256, smem_scan>>>(gxw, U2, gh2, nblk_scan);
    // Output projection: h2 @ Wout -> out
    gemm_k<128><<<148, 256, smem_g128>>>(gh2, Wout, out, nrb_out);
}

// round 9
// speedup vs baseline: 1.6553x; 1.3090x over previous
#include <cuda_runtime.h>
#include <math.h>

#define D 128
#define ND3 384
#define T_STEPS 25
#define B_ROWS 16384
#define RTOT (B_ROWS * T_STEPS)   // 409600 rows for the time-parallel GEMMs

// Scratch (static __device__ globals -- allocation-free per harness rules)
__device__ float g_xw[(size_t)RTOT * ND3];   // xW projections for current layer [B*T, 384]
__device__ float g_h1[(size_t)RTOT * D];     // layer-1 hidden sequence [B*T, 128]
__device__ float g_h2[(size_t)B_ROWS * D];   // layer-2 final hidden [B, 128]

typedef unsigned long long ull;

__device__ __forceinline__ float sigmoidf_fast(float x) {
    return 1.0f / (1.0f + __expf(-x));
}

// Packed fp32x2 helpers (Blackwell FFMA2 -- only reachable via PTX fma.rn.f32x2)
__device__ __forceinline__ ull dup2(float v) {
    ull r;
    asm("mov.b64 %0, {%1, %1};" : "=l"(r) : "f"(v));
    return r;
}
__device__ __forceinline__ void unpack2(ull v, float& lo, float& hi) {
    asm("mov.b64 {%0, %1}, %2;" : "=f"(lo), "=f"(hi) : "l"(v));
}
__device__ __forceinline__ ull ffma2(ull a, ull b, ull c) {
    ull d;
    asm("fma.rn.f32x2 %0, %1, %2, %3;" : "=l"(d) : "l"(a), "l"(b), "l"(c));
    return d;
}

// ---------------------------------------------------------------------------
// Row-parallel GEMM via FFMA2: G[r, c] = sum_k X[r, k] * W[k, c]
// 64-row blocks, 256 threads = 8 warps; warp w owns rows w*8..w*8+7 (R=8).
// Lane tx owns column pairs (64j + 2tx, +1), j = 0..NC/64-1 (all NC cols).
// Deep row-amortization (8 rows per b-load) makes the inner loop FMA-bound:
// per k per SM, LDS phases = 8*(8 bcast + 2*PJ) vs FMA = 2*8*PJ*2 SMSP-cyc.
// X tile stored plain (4B); broadcast a duplicated in regs via mov.b64 (ALU).
// ---------------------------------------------------------------------------
template <int NC>
__global__ void __launch_bounds__(256, 1)
gemm_k(const float* __restrict__ X, const float* __restrict__ W,
       float* __restrict__ G, int nrowblocks)
{
    constexpr int PJ = NC / 64;       // column pairs per thread
    constexpr int NCH = NC / 2;       // pair-stride of one W row
    extern __shared__ float sm[];
    float* Ws = sm;                   // [128*NC]
    float* xs = sm + D * NC;          // [64*128] plain
    const ull* Wsv = (const ull*)Ws;

    const int tid = threadIdx.x;
    {   // stage W (vectorized)
        const float4* Wv = (const float4*)W;
        float4* Wst = (float4*)Ws;
        for (int i = tid; i < D * NC / 4; i += 256) Wst[i] = Wv[i];
    }

    const int tx = tid & 31;
    const int ty = tid >> 5;
    const int r0 = ty * 8;            // 8 rows per thread (whole warp same rows)

    for (int rb = blockIdx.x; rb < nrowblocks; rb += gridDim.x) {
        const size_t rowbase = (size_t)rb * 64;
        __syncthreads();   // prior block's xs reads done
        {   // stage X block: 64*128 floats = 2048 float4s
            const float4* Xv = (const float4*)(X + rowbase * D);
            float4* xsv = (float4*)xs;
            for (int i = tid; i < 64 * D / 4; i += 256) xsv[i] = Xv[i];
        }
        __syncthreads();

        ull acc[8][PJ];
        #pragma unroll
        for (int i = 0; i < 8; i++)
            #pragma unroll
            for (int j = 0; j < PJ; j++) acc[i][j] = 0ULL;

        #pragma unroll 2
        for (int k = 0; k < D; k++) {
            ull a2[8];
            #pragma unroll
            for (int i = 0; i < 8; i++) a2[i] = dup2(xs[(r0 + i) * D + k]);
            #pragma unroll
            for (int j = 0; j < PJ; j++) {
                const ull b = Wsv[k * NCH + 32 * j + tx];   // cols (64j+2tx, +1)
                #pragma unroll
                for (int i = 0; i < 8; i++) acc[i][j] = ffma2(a2[i], b, acc[i][j]);
            }
        }

        #pragma unroll
        for (int i = 0; i < 8; i++) {
            float2* G2 = (float2*)(G + (rowbase + r0 + i) * NC);
            #pragma unroll
            for (int j = 0; j < PJ; j++) {
                float lo, hi; unpack2(acc[i][j], lo, hi);
                G2[32 * j + tx] = make_float2(lo, hi);
            }
        }
    }
}

// ---------------------------------------------------------------------------
// GRU scan via FFMA2, same 64-row/8-rows-per-thread structure.
// 256 blocks of 64 rows -> 128 CTAs x exactly 2 blocks. U resident in smem
// (staged once per CTA, 192KB); h state (64x128 plain, 32KB) exchanged
// through smem each step. Epilogue reads/writes h as float2 pairs.
// ---------------------------------------------------------------------------
template <bool STORE_SEQ>
__global__ void __launch_bounds__(256, 1)
gru_scan(const float* __restrict__ G, const float* __restrict__ U,
         float* __restrict__ Hout, int nblocks)
{
    constexpr int NDH = ND3 / 2;   // 192 pair-stride
    extern __shared__ float sm[];
    float* Us = sm;                // [128*384]
    float* hs = sm + D * ND3;      // [64*128] plain
    const ull* Usv = (const ull*)Us;

    const int tid = threadIdx.x;
    {   // stage U once per CTA
        const float4* Uv = (const float4*)U;
        float4* Ust = (float4*)Us;
        for (int i = tid; i < D * ND3 / 4; i += 256) Ust[i] = Uv[i];
    }

    const int tx = tid & 31;
    const int ty = tid >> 5;
    const int r0 = ty * 8;         // 8 rows per thread

    for (int blk = blockIdx.x; blk < nblocks; blk += gridDim.x) {
        const size_t rowbase = (size_t)blk * 64;

        __syncthreads();           // prior block's epilogue writes done
        for (int i = tid; i < 64 * D; i += 256) hs[i] = 0.0f;

        for (int t = 0; t < T_STEPS; t++) {
            __syncthreads();       // hs (and Us on first pass) visible

            ull acc[8][6];
            #pragma unroll
            for (int i = 0; i < 8; i++)
                #pragma unroll
                for (int j = 0; j < 6; j++) acc[i][j] = 0ULL;

            #pragma unroll 2
            for (int k = 0; k < D; k++) {
                ull a2[8];
                #pragma unroll
                for (int i = 0; i < 8; i++) a2[i] = dup2(hs[(r0 + i) * D + k]);
                #pragma unroll
                for (int j = 0; j < 6; j++) {
                    const ull b = Usv[k * NDH + 32 * j + tx];
                    #pragma unroll
                    for (int i = 0; i < 8; i++) acc[i][j] = ffma2(a2[i], b, acc[i][j]);
                }
            }

            __syncthreads();       // all hs reads complete before updates

            #pragma unroll
            for (int i = 0; i < 8; i++) {
                const int row = r0 + i;
                const size_t grow = ((rowbase + row) * T_STEPS + t);
                const float2* G2 = (const float2*)(G + grow * ND3);
                float2* hs2 = (float2*)(hs + row * D);
                #pragma unroll
                for (int jz = 0; jz < 2; jz++) {
                    // column pair c0 = 64*jz + 2*tx, c0+1
                    const float2 xz = G2[      32 * jz + tx];
                    const float2 xr = G2[ 64 + 32 * jz + tx];
                    const float2 xh = G2[128 + 32 * jz + tx];
                    float uz0, uz1, ur0, ur1, uh0, uh1;
                    unpack2(acc[i][jz],     uz0, uz1);
                    unpack2(acc[i][2 + jz], ur0, ur1);
                    unpack2(acc[i][4 + jz], uh0, uh1);
                    const float z0 = sigmoidf_fast(xz.x + uz0);
                    const float z1 = sigmoidf_fast(xz.y + uz1);
                    const float rr0 = sigmoidf_fast(xr.x + ur0);
                    const float rr1 = sigmoidf_fast(xr.y + ur1);
                    const float hh0 = xh.x + rr0 * uh0;   // reset_after, linear act
                    const float hh1 = xh.y + rr1 * uh1;
                    const float2 hold = hs2[32 * jz + tx];
                    const float n0 = z0 * hold.x + (1.0f - z0) * hh0;
                    const float n1 = z1 * hold.y + (1.0f - z1) * hh1;
                    hs2[32 * jz + tx] = make_float2(n0, n1);
                    if (STORE_SEQ) {
                        float2* H2 = (float2*)(Hout + grow * D);
                        H2[32 * jz + tx] = make_float2(n0, n1);
                    } else if (t == T_STEPS - 1) {
                        float2* H2 = (float2*)(Hout + (rowbase + row) * D);
                        H2[32 * jz + tx] = make_float2(n0, n1);
                    }
                }
            }
        }
    }
}

// ---------------------------------------------------------------------------
// kernel_launch: 5 graph-capturable launches, no allocs, no syncs.
// Inputs (metadata order): x, W1, U1, W2, U2, Wout. Output: [16384,128] f32.
// ---------------------------------------------------------------------------
extern "C" void kernel_launch(void* const* d_in, const int* in_sizes, int n_in,
                              void* d_out, int out_size)
{
    const float* x    = (const float*)d_in[0];
    const float* W1   = (const float*)d_in[1];
    const float* U1   = (const float*)d_in[2];
    const float* W2   = (const float*)d_in[3];
    const float* U2   = (const float*)d_in[4];
    const float* Wout = (const float*)d_in[5];
    float* out = (float*)d_out;

    void *p_xw = nullptr, *p_h1 = nullptr, *p_h2 = nullptr;
    cudaGetSymbolAddress(&p_xw, g_xw);
    cudaGetSymbolAddress(&p_h1, g_h1);
    cudaGetSymbolAddress(&p_h2, g_h2);
    float* gxw = (float*)p_xw;
    float* gh1 = (float*)p_h1;
    float* gh2 = (float*)p_h2;

    // smem sizes (all <= 229376 B, validated opt-in limit on this part)
    const size_t smem_g384 = (size_t)D * ND3 * 4 + 64 * D * 4;   // 192KB + 32KB = 229376
    const size_t smem_g128 = (size_t)D * 128 * 4 + 64 * D * 4;   // 64KB + 32KB
    const size_t smem_scan = (size_t)D * ND3 * 4 + 64 * D * 4;   // 192KB + 32KB

    cudaFuncSetAttribute(gemm_k<384>, cudaFuncAttributeMaxDynamicSharedMemorySize, (int)smem_g384);
    cudaFuncSetAttribute(gemm_k<128>, cudaFuncAttributeMaxDynamicSharedMemorySize, (int)smem_g128);
    cudaFuncSetAttribute(gru_scan<true>,  cudaFuncAttributeMaxDynamicSharedMemorySize, (int)smem_scan);
    cudaFuncSetAttribute(gru_scan<false>, cudaFuncAttributeMaxDynamicSharedMemorySize, (int)smem_scan);

    const int nrb_big   = RTOT / 64;    // 6400 row-blocks of 64
    const int nrb_out   = B_ROWS / 64;  // 256
    const int nblk_scan = B_ROWS / 64;  // 256 scan blocks of 64 rows

    // Layer 1: x @ W1 -> g_xw
    gemm_k<384><<<148, 256, smem_g384>>>(x, W1, gxw, nrb_big);
    // Layer 1 scan (store full sequence)
    gru_scan<true><<<128, 256, smem_scan>>>(gxw, U1, gh1, nblk_scan);
    // Layer 2: h1seq @ W2 -> g_xw (reuse)
    gemm_k<384><<<148, 256, smem_g384>>>(gh1, W2, gxw, nrb_big);
    // Layer 2 scan (final state only)
    gru_scan<false><<<128, 256, smem_scan>>>(gxw, U2, gh2, nblk_scan);
    // Output projection: h2 @ Wout -> out
    gemm_k<128><<<128, 256, smem_g128>>>(gh2, Wout, out, nrb_out);
}